// round 7
// baseline (speedup 1.0000x reference)
#include <cuda_runtime.h>
#include <math.h>

// Problem constants (fixed by setup_inputs)
#define B_  32
#define K_  16
#define T_  30
#define N_  128
#define n_  20
#define NN  (N_ * n_)        // 2560 nodes per batch
#define CHUNK0 256           // nodes cached in smem for phase A

#define YAW_THRESH  1.0471975511965976f   // pi/3
#define INF_F       __int_as_float(0x7f800000)

__device__ __forceinline__ float fast_sqrt(float x) {
    float r;
    asm("sqrt.approx.f32 %0, %1;" : "=f"(r) : "f"(x));
    return r;
}

// One block per (b, k); 1024 threads = 32 warps; warps 0..29 <-> timesteps.
//
// cost = relu(dist - 2) + relu(|wrap(yaw_n - yaw_p)| - pi/3); masked -> inf.
// yaw = -atan2(dx, dy) is a reflection of the direction angle, so
// |wrapped yaw diff| == angle(u, v) between raw direction vectors
// (segment starts / t = 0 map to direction (0, 1)).
// Exact-zero (no transcendentals): d2 <= 4 AND dot >= 0 AND cross^2 <= 3*dot^2
// (tan(pi/3)^2 == 3). Masked nodes carry x = +inf -> d2 = inf: zero test
// fails and the cost path yields +inf, no explicit flag needed.
//
// Phase 0: build s_nd[256] once per block (prep shared by all 30 warps).
// Phase A: warp t scans the 256 cached nodes in two 128-node sub-chunks
//          (smem loads only); zero hit -> min finalized (cost >= 0).
// Phase B: rare unresolved timesteps scan nodes [256, NN) with all 1024
//          threads in parallel (zero-test first, atan2 only when needed).
__global__ __launch_bounds__(1024)
void consistency_kernel(const float* __restrict__ preds,
                        const float* __restrict__ cn,
                        const int*   __restrict__ mask,
                        float* __restrict__ out) {
    const int bk = blockIdx.x;
    const int b  = bk >> 4;                 // / K_

    const float2* cnb = (const float2*)cn + (size_t)b * NN;
    const int*    mb  = mask + (size_t)b * NN;
    const float2* pp  = (const float2*)preds + (size_t)bk * T_;

    __shared__ float4 s_nd[CHUNK0];         // 4 KB
    __shared__ float  s_min[32];
    __shared__ int    s_unres[32];
    __shared__ int    s_ucnt;
    __shared__ float  s_red[32];

    const int tid  = threadIdx.x;
    const int warp = tid >> 5;
    const int lane = tid & 31;

    if (tid == 0) s_ucnt = 0;
    if (warp >= T_ && lane == 0 && warp < 32) s_min[warp] = 0.0f; // pad t=30,31

    // ---------------- Phase 0: cache first 256 nodes ----------------
    if (tid < CHUNK0) {
        const int idx = tid;
        float2 p = cnb[idx];
        float2 q = cnb[idx > 0 ? idx - 1 : 0];
        int    m = mb[idx];
        bool start = (idx % n_ == 0);
        float ux = start ? 0.0f : p.x - q.x;
        float uy = start ? 1.0f : p.y - q.y;
        float x  = (m == 1) ? INF_F : p.x;   // masked -> d2 = +inf
        s_nd[idx] = make_float4(x, p.y, ux, uy);
    }
    __syncthreads();

    // ---------------- Phase A: warp-per-timestep smem scan ----------------
    if (warp < T_) {
        const int t = warp;
        const float2 pt = pp[t];
        float vx = 0.0f, vy = 1.0f;          // yaw 0 <-> direction (0, 1)
        if (t != 0) {
            float2 pm = pp[t - 1];
            vx = pt.x - pm.x;
            vy = pt.y - pm.y;
        }

        float lmin = INF_F;
        bool  resolved = false;

        #pragma unroll
        for (int sub = 0; sub < CHUNK0; sub += 128) {
            float d2[4], dt[4], cr[4];
            bool  anyzero = false;

            #pragma unroll
            for (int j = 0; j < 4; ++j) {
                float4 nd = s_nd[sub + j * 32 + lane];
                float dx = nd.x - pt.x;
                float dy = nd.y - pt.y;
                d2[j] = fmaf(dx, dx, dy * dy);
                dt[j] = fmaf(nd.z, vx, nd.w * vy);    // dot(u, v)
                cr[j] = fmaf(nd.z, vy, -nd.w * vx);   // cross(u, v)
                anyzero |= (d2[j] <= 4.0f) && (dt[j] >= 0.0f) &&
                           (cr[j] * cr[j] <= 3.0f * dt[j] * dt[j]);
            }

            if (__ballot_sync(0xffffffffu, anyzero)) {
                lmin = 0.0f;
                resolved = true;
                break;
            }

            // zero-free sub-chunk: full costs (masked -> d2 = inf -> c = inf)
            #pragma unroll
            for (int j = 0; j < 4; ++j) {
                float cd = (d2[j] <= 4.0f) ? 0.0f : (fast_sqrt(d2[j]) - 2.0f);
                float a  = atan2f(fabsf(cr[j]), dt[j]);
                lmin = fminf(lmin, cd + fmaxf(a - YAW_THRESH, 0.0f));
            }
        }

        if (resolved) {
            if (lane == 0) s_min[t] = 0.0f;
        } else {
            lmin = fminf(lmin, __shfl_xor_sync(0xffffffffu, lmin, 16));
            lmin = fminf(lmin, __shfl_xor_sync(0xffffffffu, lmin, 8));
            lmin = fminf(lmin, __shfl_xor_sync(0xffffffffu, lmin, 4));
            lmin = fminf(lmin, __shfl_xor_sync(0xffffffffu, lmin, 2));
            lmin = fminf(lmin, __shfl_xor_sync(0xffffffffu, lmin, 1));
            if (lane == 0) {
                s_min[t] = lmin;
                int pos = atomicAdd(&s_ucnt, 1);
                s_unres[pos] = t;
            }
        }
    }
    __syncthreads();

    // ---------------- Phase B: block-cooperative straggler scans ----------
    const int ucnt = s_ucnt;
    for (int u = 0; u < ucnt; ++u) {
        const int t = s_unres[u];
        const float2 pt = pp[t];
        float vx = 0.0f, vy = 1.0f;
        if (t != 0) {
            float2 pm = pp[t - 1];
            vx = pt.x - pm.x;
            vy = pt.y - pm.y;
        }

        float lmin = INF_F;
        for (int idx = CHUNK0 + tid; idx < NN; idx += 1024) {
            float2 p = cnb[idx];
            float2 q = cnb[idx - 1];
            int    m = mb[idx];
            bool start = (idx % n_ == 0);
            float ux = start ? 0.0f : p.x - q.x;
            float uy = start ? 1.0f : p.y - q.y;
            float x  = (m == 1) ? INF_F : p.x;

            float dx = x - pt.x;
            float dy = p.y - pt.y;
            float d2 = fmaf(dx, dx, dy * dy);
            float dt = fmaf(ux, vx, uy * vy);
            float cr = fmaf(ux, vy, -uy * vx);

            if ((d2 <= 4.0f) && (dt >= 0.0f) && (cr * cr <= 3.0f * dt * dt)) {
                lmin = 0.0f;
                break;
            }
            float cd = (d2 <= 4.0f) ? 0.0f : (fast_sqrt(d2) - 2.0f);
            float a  = atan2f(fabsf(cr), dt);
            lmin = fminf(lmin, cd + fmaxf(a - YAW_THRESH, 0.0f));
        }

        lmin = fminf(lmin, __shfl_xor_sync(0xffffffffu, lmin, 16));
        lmin = fminf(lmin, __shfl_xor_sync(0xffffffffu, lmin, 8));
        lmin = fminf(lmin, __shfl_xor_sync(0xffffffffu, lmin, 4));
        lmin = fminf(lmin, __shfl_xor_sync(0xffffffffu, lmin, 2));
        lmin = fminf(lmin, __shfl_xor_sync(0xffffffffu, lmin, 1));
        if (lane == 0) s_red[warp] = lmin;
        __syncthreads();
        if (tid < 32) {
            float v = s_red[tid];
            v = fminf(v, __shfl_xor_sync(0xffffffffu, v, 16));
            v = fminf(v, __shfl_xor_sync(0xffffffffu, v, 8));
            v = fminf(v, __shfl_xor_sync(0xffffffffu, v, 4));
            v = fminf(v, __shfl_xor_sync(0xffffffffu, v, 2));
            v = fminf(v, __shfl_xor_sync(0xffffffffu, v, 1));
            if (tid == 0) s_min[t] = fminf(s_min[t], v);
        }
        __syncthreads();
    }

    // ---------------- Sum over T (deterministic shfl tree) ----------------
    if (tid < 32) {
        float v = s_min[tid];
        v += __shfl_xor_sync(0xffffffffu, v, 16);
        v += __shfl_xor_sync(0xffffffffu, v, 8);
        v += __shfl_xor_sync(0xffffffffu, v, 4);
        v += __shfl_xor_sync(0xffffffffu, v, 2);
        v += __shfl_xor_sync(0xffffffffu, v, 1);
        if (tid == 0) out[bk] = v;
    }
}

extern "C" void kernel_launch(void* const* d_in, const int* in_sizes, int n_in,
                              void* d_out, int out_size) {
    const float* preds = (const float*)d_in[0];
    const float* cn    = (const float*)d_in[1];
    const int*   mask  = (const int*)d_in[2];
    float* out = (float*)d_out;

    consistency_kernel<<<B_ * K_, 1024>>>(preds, cn, mask, out);
}